// round 11
// baseline (speedup 1.0000x reference)
#include <cuda_runtime.h>
#include <math.h>

// Problem constants (fixed shapes)
#define B_  4
#define C_  32
#define T_  48
#define N_  2000
#define E_  16000
#define BT_ (B_ * T_)   // 192

#define PTSB 256        // points per conv block
#define NBLK 8          // ceil(2000/256)
#define XWSTRIDE 34     // transpose tile row stride (words, EVEN for ST.64)

typedef unsigned long long ull;

// ---------------------------------------------------------------------------
// Scratch (device globals)
// ---------------------------------------------------------------------------
__device__ float g_xw[BT_ * N_ * C_];     // h = relu(conv1), layout [g][n][c]
__device__ float g_gout[BT_ * C_ * N_];   // agg output z, layout [g][c][n]
__device__ int   g_srcb[E_];
__device__ int   g_dstb[E_];
__device__ int   g_off[N_ + 1];
__device__ int   g_csr_src[E_];
__device__ float g_csr_w[E_];
__device__ float g_invdeg[N_];
__device__ float g_w2p[32 * 3 * 32];      // folded w2' : [(c1*3+kt)*32 + co]
__device__ float g_bk[3 * 32];            // per-tap bias : [kt*32 + co]

// ---------------------------------------------------------------------------
// f32x2 helpers
// ---------------------------------------------------------------------------
__device__ __forceinline__ ull dup2(float x) {
    ull r;
    unsigned u = __float_as_uint(x);
    asm("mov.b64 %0, {%1, %1};" : "=l"(r) : "r"(u));
    return r;
}
__device__ __forceinline__ ull pack2(float a, float b) {
    ull r;
    asm("mov.b64 %0, {%1, %2};" : "=l"(r)
        : "r"(__float_as_uint(a)), "r"(__float_as_uint(b)));
    return r;
}
__device__ __forceinline__ void ffma2(ull& acc, ull a, ull b) {
    asm("fma.rn.f32x2 %0, %1, %2, %0;" : "+l"(acc) : "l"(a), "l"(b));
}
__device__ __forceinline__ float2 unpack2(ull v) {
    unsigned lo, hi;
    asm("mov.b64 {%0, %1}, %2;" : "=r"(lo), "=r"(hi) : "l"(v));
    return make_float2(__uint_as_float(lo), __uint_as_float(hi));
}

// ---------------------------------------------------------------------------
// K1: conv1+relu (stage B removed — gcn_w folded into conv2's weights).
// CSR preprocessing + weight folding fused in as one extra block.
// Thread map: cog = tid&3 (co0 = cog*8), ptg = tid>>2 (4 points each).
// ---------------------------------------------------------------------------
__global__ void __launch_bounds__(256, 3) k_conv1(
    const float* __restrict__ x,
    const void*  __restrict__ edges,
    const float* __restrict__ w1,
    const float* __restrict__ b1,
    const float* __restrict__ gcn_w,
    const float* __restrict__ gcn_b,
    const float* __restrict__ w2)
{
    __shared__ __align__(16) union U {
        float pool[PTSB * XWSTRIDE];      // transpose tile [256][34]
        struct {
            int   cnt[2000];
            int   off[2000];
            float dinv[2000];
            int   wsum[8];
            int   is64;
        } prep;
    } u;
    __shared__ __align__(16) float w1s[96 * 32];   // [(ci*3+kt)*32 + co]
    __shared__ __align__(16) float b1s[32];

    int tid = threadIdx.x;

    // ---------------- fused preprocessing block ----------------
    if (blockIdx.x == NBLK) {
        if (blockIdx.y != 0 || blockIdx.z != 0) return;

        if (tid == 0) {
            const int* q = (const int*)edges;
            int ok = 1;
            #pragma unroll 1
            for (int i = 0; i < 64; i++) {
                if (q[2 * i + 1] != 0) { ok = 0; break; }
            }
            u.prep.is64 = ok;
        }
        for (int i = tid; i < N_; i += 256) u.prep.cnt[i] = 0;
        __syncthreads();
        const int is64 = u.prep.is64;

        #pragma unroll 1
        for (int e = tid; e < E_; e += 256) {
            int s, d;
            if (is64) {
                const long long* p = (const long long*)edges;
                s = (int)p[e];
                d = (int)p[E_ + e];
            } else {
                const int* p = (const int*)edges;
                s = p[e];
                d = p[E_ + e];
            }
            g_srcb[e] = s;
            g_dstb[e] = d;
            atomicAdd(&u.prep.cnt[d], 1);
        }
        __syncthreads();

        // block scan over 2000 counts (8 per thread, 256 threads)
        int lane = tid & 31, wid = tid >> 5;
        int base = tid * 8;
        int c[8];
        int sum = 0;
        #pragma unroll
        for (int i = 0; i < 8; i++) {
            int idx = base + i;
            c[i] = (idx < N_) ? u.prep.cnt[idx] : 0;
            sum += c[i];
        }
        int incl = sum;
        #pragma unroll
        for (int o = 1; o < 32; o <<= 1) {
            int v = __shfl_up_sync(0xffffffffu, incl, o);
            if (lane >= o) incl += v;
        }
        if (lane == 31) u.prep.wsum[wid] = incl;
        __syncthreads();
        int woff = 0;
        #pragma unroll
        for (int w = 0; w < 8; w++) woff += (w < wid) ? u.prep.wsum[w] : 0;
        int run = woff + incl - sum;
        #pragma unroll
        for (int i = 0; i < 8; i++) {
            int idx = base + i;
            if (idx < N_) {
                u.prep.off[idx] = run;
                g_off[idx] = run;
                float deg = (float)c[i] + 1.0f;
                u.prep.dinv[idx] = rsqrtf(deg);
                g_invdeg[idx] = 1.0f / deg;
            }
            run += c[i];
        }
        if (tid == 0) g_off[N_] = E_;
        __syncthreads();
        for (int i = tid; i < N_; i += 256) u.prep.cnt[i] = 0;
        __syncthreads();

        #pragma unroll 1
        for (int e = tid; e < E_; e += 256) {
            int s = g_srcb[e];
            int d = g_dstb[e];
            int pos = atomicAdd(&u.prep.cnt[d], 1);
            int idx = u.prep.off[d] + pos;
            g_csr_src[idx] = s;
            g_csr_w[idx] = u.prep.dinv[s] * u.prep.dinv[d];
        }

        // ---- weight folding: w2'[co,c1,kt] = sum_c2 w2[co,c2,kt]*gcn_w[c1,c2]
        #pragma unroll 1
        for (int i = tid; i < 32 * 3 * 32; i += 256) {
            int co = i & 31;
            int r  = i >> 5;        // r = c1*3 + kt
            int kt = r % 3;
            int c1 = r / 3;
            float s = 0.0f;
            #pragma unroll 8
            for (int c2 = 0; c2 < 32; c2++)
                s += w2[(co * 32 + c2) * 3 + kt] * gcn_w[c1 * 32 + c2];
            g_w2p[i] = s;
        }
        // ---- per-tap bias: bk[kt,co] = sum_c2 w2[co,c2,kt]*gcn_b[c2]
        if (tid < 96) {
            int co = tid & 31;
            int kt = tid >> 5;
            float s = 0.0f;
            #pragma unroll 8
            for (int c2 = 0; c2 < 32; c2++)
                s += w2[(co * 32 + c2) * 3 + kt] * gcn_b[c2];
            g_bk[kt * 32 + co] = s;
        }
        return;
    }

    // ---------------- conv1 + relu ----------------
    for (int i = tid; i < 96 * 32; i += 256) {
        int co = i & 31;
        int r = i >> 5;
        int kt = r % 3;
        int ci = r / 3;
        w1s[i] = w1[(co * C_ + ci) * 3 + kt];
    }
    if (tid < 32) b1s[tid] = b1[tid];
    __syncthreads();

    int cog = tid & 3;
    int ptg = tid >> 2;              // 0..63
    int co0 = cog * 8;
    int n0  = blockIdx.x * PTSB;
    int nb  = n0 + ptg * 4;
    bool alive = (nb < N_);
    int t = blockIdx.y;
    int b = blockIdx.z;

    bool v0 = (t - 1 >= 0);
    bool v2 = (t + 1 < T_);
    bool ld[3] = { v0 && alive, alive, v2 && alive };

    ull acc[4][4];
    {
        const ull* bp = (const ull*)b1s;   // pairs (2c, 2c+1)
        #pragma unroll
        for (int cp = 0; cp < 4; cp++) {
            ull bq = bp[co0 / 2 + cp];
            #pragma unroll
            for (int pt = 0; pt < 4; pt++) acc[pt][cp] = bq;
        }
    }

    const float* xrow = x + ((size_t)(b * C_ * T_) + (t - 1)) * N_ + nb;
    #pragma unroll 2
    for (int ci = 0; ci < 32; ci++) {
        const float* xr = xrow + ci * (T_ * N_);
        float4 xv[3];
        #pragma unroll
        for (int kt = 0; kt < 3; kt++) {
            xv[kt] = ld[kt] ? *(const float4*)(xr + kt * N_)
                            : make_float4(0.f, 0.f, 0.f, 0.f);
        }
        #pragma unroll
        for (int kt = 0; kt < 3; kt++) {
            ull in[4];
            in[0] = dup2(xv[kt].x); in[1] = dup2(xv[kt].y);
            in[2] = dup2(xv[kt].z); in[3] = dup2(xv[kt].w);
            const ulonglong2* wp = (const ulonglong2*)&w1s[(ci * 3 + kt) * 32 + co0];
            ulonglong2 wa = wp[0];
            ulonglong2 wb = wp[1];
            #pragma unroll
            for (int pt = 0; pt < 4; pt++) {
                ffma2(acc[pt][0], in[pt], wa.x);
                ffma2(acc[pt][1], in[pt], wa.y);
                ffma2(acc[pt][2], in[pt], wb.x);
                ffma2(acc[pt][3], in[pt], wb.y);
            }
        }
    }

    // relu -> transpose tile [pt][co], then coalesced store
    float* xwt = u.pool;
    int pl = ptg * 4;
    #pragma unroll
    for (int pt = 0; pt < 4; pt++) {
        #pragma unroll
        for (int cp = 0; cp < 4; cp++) {
            float2 v = unpack2(acc[pt][cp]);
            v.x = fmaxf(v.x, 0.0f);
            v.y = fmaxf(v.y, 0.0f);
            *(float2*)&xwt[(pl + pt) * XWSTRIDE + co0 + 2 * cp] = v;
        }
    }
    __syncthreads();

    int g = b * T_ + t;
    float* dst = g_xw + ((size_t)g * N_ + n0) * C_;
    int rows = min(PTSB, N_ - n0);
    for (int i = tid; i < rows * C_; i += 256) {
        dst[i] = xwt[(i >> 5) * XWSTRIDE + (i & 31)];
    }
}

// ---------------------------------------------------------------------------
// K2: GCN aggregation over h; 4 graphs per warp. z = aggH + invdeg*h.
// (gcn_w and gcn_b folded into conv2.) Writes g_gout transposed [g][c][n].
// ---------------------------------------------------------------------------
__global__ void __launch_bounds__(256) k_agg() {
    __shared__ __align__(16) float sbuf[4 * 256];   // [gg][lane*8+warp]
    int warp = threadIdx.x >> 5;
    int lane = threadIdx.x & 31;
    int n  = blockIdx.x * 8 + warp;
    int g0 = blockIdx.y * 4;

    int s0 = g_off[n];
    int s1 = g_off[n + 1];
    const float* __restrict__ xw0 = g_xw + (size_t)g0 * N_ * C_;
    const size_t GS = (size_t)N_ * C_;

    float acc[4] = {0.f, 0.f, 0.f, 0.f};
    int e = s0;
    for (; e + 1 < s1; e += 2) {
        int   sA = g_csr_src[e];
        int   sB = g_csr_src[e + 1];
        float wA = g_csr_w[e];
        float wB = g_csr_w[e + 1];
        float vA[4], vB[4];
        #pragma unroll
        for (int gg = 0; gg < 4; gg++) vA[gg] = __ldg(&xw0[gg * GS + sA * C_ + lane]);
        #pragma unroll
        for (int gg = 0; gg < 4; gg++) vB[gg] = __ldg(&xw0[gg * GS + sB * C_ + lane]);
        #pragma unroll
        for (int gg = 0; gg < 4; gg++) acc[gg] += wA * vA[gg] + wB * vB[gg];
    }
    if (e < s1) {
        int   sA = g_csr_src[e];
        float wA = g_csr_w[e];
        #pragma unroll
        for (int gg = 0; gg < 4; gg++) acc[gg] += wA * __ldg(&xw0[gg * GS + sA * C_ + lane]);
    }
    float idg = g_invdeg[n];
    #pragma unroll
    for (int gg = 0; gg < 4; gg++) {
        acc[gg] += idg * xw0[gg * GS + n * C_ + lane];
        sbuf[gg * 256 + lane * 8 + warp] = acc[gg];
    }
    __syncthreads();

    // transposed store: [g][c][n0..n0+7]
    int n0 = blockIdx.x * 8;
    #pragma unroll
    for (int r = 0; r < 4; r++) {
        int idx = r * 256 + threadIdx.x;
        int gg = idx >> 8;
        int c  = (idx >> 3) & 31;
        int j  = idx & 7;
        g_gout[((size_t)(g0 + gg) * C_ + c) * N_ + n0 + j] = sbuf[gg * 256 + c * 8 + j];
    }
}

// ---------------------------------------------------------------------------
// K3: conv2 with folded weights w2' and per-tap bias bk.
// Direct coalesced LDG from g_gout [g][c][n]; per-co float4 STG.128 output.
// ---------------------------------------------------------------------------
__global__ void __launch_bounds__(256, 3) k_conv2(
    const float* __restrict__ b2,
    float* __restrict__ out)
{
    __shared__ __align__(16) float w2s[96 * 32];   // folded, [(c1*3+kt)*32 + co]
    __shared__ __align__(16) float bks[3 * 32];    // [kt*32 + co]
    __shared__ __align__(16) float b2s[32];

    int tid = threadIdx.x;
    for (int i = tid; i < 96 * 32; i += 256) w2s[i] = g_w2p[i];
    if (tid < 96) bks[tid] = g_bk[tid];
    if (tid < 32) b2s[tid] = b2[tid];
    __syncthreads();

    int cog = tid & 3;
    int ptg = tid >> 2;
    int co0 = cog * 8;
    int n0  = blockIdx.x * PTSB;
    int nb  = n0 + ptg * 4;
    bool alive = (nb < N_);
    int t = blockIdx.y;
    int b = blockIdx.z;

    bool v0 = (t - 1 >= 0);
    bool v2 = (t + 1 < T_);
    bool ld[3] = { v0 && alive, alive, v2 && alive };

    ull acc[4][4];
    #pragma unroll
    for (int cp = 0; cp < 4; cp++) {
        int coA = co0 + 2 * cp;
        int coB = coA + 1;
        float biasA = b2s[coA] + bks[32 + coA]
                    + (v0 ? bks[coA] : 0.0f) + (v2 ? bks[64 + coA] : 0.0f);
        float biasB = b2s[coB] + bks[32 + coB]
                    + (v0 ? bks[coB] : 0.0f) + (v2 ? bks[64 + coB] : 0.0f);
        ull bq = pack2(biasA, biasB);
        #pragma unroll
        for (int pt = 0; pt < 4; pt++) acc[pt][cp] = bq;
    }

    // plane (t-1) for c1 = 0
    const float* gbase = g_gout + ((size_t)(b * T_) + (t - 1)) * C_ * N_ + nb;
    #pragma unroll 2
    for (int ci = 0; ci < 32; ci++) {
        const float* gr = gbase + (size_t)ci * N_;
        float4 gv[3];
        #pragma unroll
        for (int kt = 0; kt < 3; kt++) {
            gv[kt] = ld[kt] ? *(const float4*)(gr + (size_t)kt * C_ * N_)
                            : make_float4(0.f, 0.f, 0.f, 0.f);
        }
        #pragma unroll
        for (int kt = 0; kt < 3; kt++) {
            ull in[4];
            in[0] = dup2(gv[kt].x); in[1] = dup2(gv[kt].y);
            in[2] = dup2(gv[kt].z); in[3] = dup2(gv[kt].w);
            const ulonglong2* wp = (const ulonglong2*)&w2s[(ci * 3 + kt) * 32 + co0];
            ulonglong2 wa = wp[0];
            ulonglong2 wb = wp[1];
            #pragma unroll
            for (int pt = 0; pt < 4; pt++) {
                ffma2(acc[pt][0], in[pt], wa.x);
                ffma2(acc[pt][1], in[pt], wa.y);
                ffma2(acc[pt][2], in[pt], wb.x);
                ffma2(acc[pt][3], in[pt], wb.y);
            }
        }
    }

    if (alive) {
        #pragma unroll
        for (int cp = 0; cp < 4; cp++) {
            float2 v0f = unpack2(acc[0][cp]);
            float2 v1f = unpack2(acc[1][cp]);
            float2 v2f = unpack2(acc[2][cp]);
            float2 v3f = unpack2(acc[3][cp]);
            int coA = co0 + 2 * cp;
            int coB = coA + 1;
            float4 lo = make_float4(v0f.x, v1f.x, v2f.x, v3f.x);
            float4 hi = make_float4(v0f.y, v1f.y, v2f.y, v3f.y);
            *(float4*)(out + ((size_t)(b * C_ + coA) * T_ + t) * N_ + nb) = lo;
            *(float4*)(out + ((size_t)(b * C_ + coB) * T_ + t) * N_ + nb) = hi;
        }
    }
}

// ---------------------------------------------------------------------------
// Launcher
// ---------------------------------------------------------------------------
extern "C" void kernel_launch(void* const* d_in, const int* in_sizes, int n_in,
                              void* d_out, int out_size) {
    const float* x     = (const float*)d_in[0];
    const void*  edges = d_in[1];
    const float* w1    = (const float*)d_in[2];
    const float* b1    = (const float*)d_in[3];
    const float* gcn_w = (const float*)d_in[4];
    const float* gcn_b = (const float*)d_in[5];
    const float* w2    = (const float*)d_in[6];
    const float* b2    = (const float*)d_in[7];
    float* out = (float*)d_out;

    dim3 g1(NBLK + 1, T_, B_);       // +1 block does CSR prep + weight folding
    k_conv1<<<g1, 256>>>(x, edges, w1, b1, gcn_w, gcn_b, w2);

    dim3 ga(N_ / 8, BT_ / 4);
    k_agg<<<ga, 256>>>();

    dim3 g2(NBLK, T_, B_);
    k_conv2<<<g2, 256>>>(b2, out);
}

// round 12
// speedup vs baseline: 1.0213x; 1.0213x over previous
#include <cuda_runtime.h>
#include <math.h>

// Problem constants (fixed shapes)
#define B_  4
#define C_  32
#define T_  48
#define N_  2000
#define E_  16000
#define BT_ (B_ * T_)   // 192

#define PTS1 64         // points per conv1 block (x 2 t's)
#define NBLK1 32        // ceil(2000/64) -> 31.25 -> 32
#define PTSB 256        // points per conv2 block
#define NBLK2 8         // ceil(2000/256)
#define XWSTRIDE 34     // transpose tile row stride (words, EVEN for ST.64)

typedef unsigned long long ull;

// ---------------------------------------------------------------------------
// Scratch (device globals)
// ---------------------------------------------------------------------------
__device__ float g_xw[BT_ * N_ * C_];     // h = relu(conv1), layout [g][n][c]
__device__ float g_gout[BT_ * C_ * N_];   // agg output z, layout [g][c][n]
__device__ int   g_srcb[E_];
__device__ int   g_dstb[E_];
__device__ int   g_off[N_ + 1];
__device__ int   g_csr_src[E_];
__device__ float g_csr_w[E_];
__device__ float g_invdeg[N_];
__device__ float g_w2p[32 * 3 * 32];      // folded w2' : [(c1*3+kt)*32 + co]
__device__ float g_bk[3 * 32];            // per-tap bias : [kt*32 + co]

// ---------------------------------------------------------------------------
// f32x2 helpers
// ---------------------------------------------------------------------------
__device__ __forceinline__ ull dup2(float x) {
    ull r;
    unsigned u = __float_as_uint(x);
    asm("mov.b64 %0, {%1, %1};" : "=l"(r) : "r"(u));
    return r;
}
__device__ __forceinline__ ull pack2(float a, float b) {
    ull r;
    asm("mov.b64 %0, {%1, %2};" : "=l"(r)
        : "r"(__float_as_uint(a)), "r"(__float_as_uint(b)));
    return r;
}
__device__ __forceinline__ void ffma2(ull& acc, ull a, ull b) {
    asm("fma.rn.f32x2 %0, %1, %2, %0;" : "+l"(acc) : "l"(a), "l"(b));
}
__device__ __forceinline__ float2 unpack2(ull v) {
    unsigned lo, hi;
    asm("mov.b64 {%0, %1}, %2;" : "=r"(lo), "=r"(hi) : "l"(v));
    return make_float2(__uint_as_float(lo), __uint_as_float(hi));
}

// ---------------------------------------------------------------------------
// K1: conv1+relu, 2 temporal outputs per block sharing a 4-plane x window.
// CSR preprocessing + weight folding fused in as one extra block.
// Thread map: cog = tid&7 (co0 = cog*4), ptg = tid>>3 (2 points each).
// acc[t][pt][cp]: f32x2 over channel pair (co0+2cp, co0+2cp+1).
// ---------------------------------------------------------------------------
__global__ void __launch_bounds__(256, 3) k_conv1(
    const float* __restrict__ x,
    const void*  __restrict__ edges,
    const float* __restrict__ w1,
    const float* __restrict__ b1,
    const float* __restrict__ gcn_w,
    const float* __restrict__ gcn_b,
    const float* __restrict__ w2)
{
    __shared__ __align__(16) union U {
        float pool[2 * PTS1 * XWSTRIDE];  // 2 transpose tiles [64][34]
        struct {
            int   cnt[2000];
            int   off[2000];
            float dinv[2000];
            int   wsum[8];
            int   is64;
        } prep;
    } u;
    __shared__ __align__(16) float w1s[96 * 32];   // [(ci*3+kt)*32 + co]
    __shared__ __align__(16) float b1s[32];

    int tid = threadIdx.x;

    // ---------------- fused preprocessing block ----------------
    if (blockIdx.x == NBLK1) {
        if (blockIdx.y != 0 || blockIdx.z != 0) return;

        if (tid == 0) {
            const int* q = (const int*)edges;
            int ok = 1;
            #pragma unroll 1
            for (int i = 0; i < 64; i++) {
                if (q[2 * i + 1] != 0) { ok = 0; break; }
            }
            u.prep.is64 = ok;
        }
        for (int i = tid; i < N_; i += 256) u.prep.cnt[i] = 0;
        __syncthreads();
        const int is64 = u.prep.is64;

        #pragma unroll 1
        for (int e = tid; e < E_; e += 256) {
            int s, d;
            if (is64) {
                const long long* p = (const long long*)edges;
                s = (int)p[e];
                d = (int)p[E_ + e];
            } else {
                const int* p = (const int*)edges;
                s = p[e];
                d = p[E_ + e];
            }
            g_srcb[e] = s;
            g_dstb[e] = d;
            atomicAdd(&u.prep.cnt[d], 1);
        }
        __syncthreads();

        // block scan over 2000 counts (8 per thread, 256 threads)
        int lane = tid & 31, wid = tid >> 5;
        int base = tid * 8;
        int c[8];
        int sum = 0;
        #pragma unroll
        for (int i = 0; i < 8; i++) {
            int idx = base + i;
            c[i] = (idx < N_) ? u.prep.cnt[idx] : 0;
            sum += c[i];
        }
        int incl = sum;
        #pragma unroll
        for (int o = 1; o < 32; o <<= 1) {
            int v = __shfl_up_sync(0xffffffffu, incl, o);
            if (lane >= o) incl += v;
        }
        if (lane == 31) u.prep.wsum[wid] = incl;
        __syncthreads();
        int woff = 0;
        #pragma unroll
        for (int w = 0; w < 8; w++) woff += (w < wid) ? u.prep.wsum[w] : 0;
        int run = woff + incl - sum;
        #pragma unroll
        for (int i = 0; i < 8; i++) {
            int idx = base + i;
            if (idx < N_) {
                u.prep.off[idx] = run;
                g_off[idx] = run;
                float deg = (float)c[i] + 1.0f;
                u.prep.dinv[idx] = rsqrtf(deg);
                g_invdeg[idx] = 1.0f / deg;
            }
            run += c[i];
        }
        if (tid == 0) g_off[N_] = E_;
        __syncthreads();
        for (int i = tid; i < N_; i += 256) u.prep.cnt[i] = 0;
        __syncthreads();

        #pragma unroll 1
        for (int e = tid; e < E_; e += 256) {
            int s = g_srcb[e];
            int d = g_dstb[e];
            int pos = atomicAdd(&u.prep.cnt[d], 1);
            int idx = u.prep.off[d] + pos;
            g_csr_src[idx] = s;
            g_csr_w[idx] = u.prep.dinv[s] * u.prep.dinv[d];
        }

        // ---- weight folding: w2'[co,c1,kt] = sum_c2 w2[co,c2,kt]*gcn_w[c1,c2]
        #pragma unroll 1
        for (int i = tid; i < 32 * 3 * 32; i += 256) {
            int co = i & 31;
            int r  = i >> 5;        // r = c1*3 + kt
            int kt = r % 3;
            int c1 = r / 3;
            float s = 0.0f;
            #pragma unroll 8
            for (int c2 = 0; c2 < 32; c2++)
                s += w2[(co * 32 + c2) * 3 + kt] * gcn_w[c1 * 32 + c2];
            g_w2p[i] = s;
        }
        // ---- per-tap bias: bk[kt,co] = sum_c2 w2[co,c2,kt]*gcn_b[c2]
        if (tid < 96) {
            int co = tid & 31;
            int kt = tid >> 5;
            float s = 0.0f;
            #pragma unroll 8
            for (int c2 = 0; c2 < 32; c2++)
                s += w2[(co * 32 + c2) * 3 + kt] * gcn_b[c2];
            g_bk[kt * 32 + co] = s;
        }
        return;
    }

    // ---------------- conv1 + relu (2 t's per block) ----------------
    for (int i = tid; i < 96 * 32; i += 256) {
        int co = i & 31;
        int r = i >> 5;
        int kt = r % 3;
        int ci = r / 3;
        w1s[i] = w1[(co * C_ + ci) * 3 + kt];
    }
    if (tid < 32) b1s[tid] = b1[tid];
    __syncthreads();

    int cog = tid & 7;               // 8 channel groups of 4
    int ptg = tid >> 3;              // 0..31, 2 points each
    int co0 = cog * 4;
    int n0  = blockIdx.x * PTS1;
    int nb  = n0 + ptg * 2;
    bool alive = (nb < N_);
    int t0 = blockIdx.y * 2;         // outputs t0, t0+1
    int b  = blockIdx.z;

    // plane validity: planes j=0..3 are global t = t0-1+j
    bool pv[4];
    pv[0] = (t0 > 0) && alive;
    pv[1] = alive;
    pv[2] = alive;
    pv[3] = (t0 + 2 < T_) && alive;

    ull acc[2][2][2];
    {
        const ull* bp = (const ull*)b1s;   // pairs (2c, 2c+1)
        #pragma unroll
        for (int cp = 0; cp < 2; cp++) {
            ull bq = bp[co0 / 2 + cp];
            #pragma unroll
            for (int tt = 0; tt < 2; tt++)
                #pragma unroll
                for (int pt = 0; pt < 2; pt++) acc[tt][pt][cp] = bq;
        }
    }

    // pointer to plane (t0-1), ci=0
    const float* xrow = x + ((size_t)(b * C_ * T_) + (t0 - 1)) * N_ + nb;
    #pragma unroll 2
    for (int ci = 0; ci < 32; ci++) {
        const float* xr = xrow + ci * (T_ * N_);
        float2 xv[4];
        #pragma unroll
        for (int j = 0; j < 4; j++) {
            xv[j] = pv[j] ? *(const float2*)(xr + j * N_) : make_float2(0.f, 0.f);
        }
        ull ind[4][2];
        #pragma unroll
        for (int j = 0; j < 4; j++) {
            ind[j][0] = dup2(xv[j].x);
            ind[j][1] = dup2(xv[j].y);
        }
        #pragma unroll
        for (int kt = 0; kt < 3; kt++) {
            ulonglong2 w = *(const ulonglong2*)&w1s[(ci * 3 + kt) * 32 + co0];
            #pragma unroll
            for (int tt = 0; tt < 2; tt++) {
                int j = tt + kt;
                #pragma unroll
                for (int pt = 0; pt < 2; pt++) {
                    ffma2(acc[tt][pt][0], ind[j][pt], w.x);
                    ffma2(acc[tt][pt][1], ind[j][pt], w.y);
                }
            }
        }
    }

    // relu -> transpose tiles [t][pt][co], then coalesced store
    float* xwt = u.pool;
    #pragma unroll
    for (int tt = 0; tt < 2; tt++) {
        #pragma unroll
        for (int pt = 0; pt < 2; pt++) {
            int row = ptg * 2 + pt;
            #pragma unroll
            for (int cp = 0; cp < 2; cp++) {
                float2 v = unpack2(acc[tt][pt][cp]);
                v.x = fmaxf(v.x, 0.0f);
                v.y = fmaxf(v.y, 0.0f);
                *(float2*)&xwt[(tt * PTS1 + row) * XWSTRIDE + co0 + 2 * cp] = v;
            }
        }
    }
    __syncthreads();

    int g0 = b * T_ + t0;
    int rows = min(PTS1, N_ - n0);
    int total = rows * C_;
    float* dst0 = g_xw + ((size_t)g0 * N_ + n0) * C_;
    float* dst1 = g_xw + ((size_t)(g0 + 1) * N_ + n0) * C_;
    for (int i = tid; i < total; i += 256) {
        int r = i >> 5, c = i & 31;
        dst0[i] = xwt[r * XWSTRIDE + c];
        dst1[i] = xwt[(PTS1 + r) * XWSTRIDE + c];
    }
}

// ---------------------------------------------------------------------------
// K2: GCN aggregation over h; 4 graphs per warp. z = aggH + invdeg*h.
// Writes g_gout transposed [g][c][n].
// ---------------------------------------------------------------------------
__global__ void __launch_bounds__(256) k_agg() {
    __shared__ __align__(16) float sbuf[4 * 256];   // [gg][lane*8+warp]
    int warp = threadIdx.x >> 5;
    int lane = threadIdx.x & 31;
    int n  = blockIdx.x * 8 + warp;
    int g0 = blockIdx.y * 4;

    int s0 = g_off[n];
    int s1 = g_off[n + 1];
    const float* __restrict__ xw0 = g_xw + (size_t)g0 * N_ * C_;
    const size_t GS = (size_t)N_ * C_;

    float acc[4] = {0.f, 0.f, 0.f, 0.f};
    int e = s0;
    for (; e + 1 < s1; e += 2) {
        int   sA = g_csr_src[e];
        int   sB = g_csr_src[e + 1];
        float wA = g_csr_w[e];
        float wB = g_csr_w[e + 1];
        float vA[4], vB[4];
        #pragma unroll
        for (int gg = 0; gg < 4; gg++) vA[gg] = __ldg(&xw0[gg * GS + sA * C_ + lane]);
        #pragma unroll
        for (int gg = 0; gg < 4; gg++) vB[gg] = __ldg(&xw0[gg * GS + sB * C_ + lane]);
        #pragma unroll
        for (int gg = 0; gg < 4; gg++) acc[gg] += wA * vA[gg] + wB * vB[gg];
    }
    if (e < s1) {
        int   sA = g_csr_src[e];
        float wA = g_csr_w[e];
        #pragma unroll
        for (int gg = 0; gg < 4; gg++) acc[gg] += wA * __ldg(&xw0[gg * GS + sA * C_ + lane]);
    }
    float idg = g_invdeg[n];
    #pragma unroll
    for (int gg = 0; gg < 4; gg++) {
        acc[gg] += idg * xw0[gg * GS + n * C_ + lane];
        sbuf[gg * 256 + lane * 8 + warp] = acc[gg];
    }
    __syncthreads();

    // transposed store: [g][c][n0..n0+7]
    int n0 = blockIdx.x * 8;
    #pragma unroll
    for (int r = 0; r < 4; r++) {
        int idx = r * 256 + threadIdx.x;
        int gg = idx >> 8;
        int c  = (idx >> 3) & 31;
        int j  = idx & 7;
        g_gout[((size_t)(g0 + gg) * C_ + c) * N_ + n0 + j] = sbuf[gg * 256 + c * 8 + j];
    }
}

// ---------------------------------------------------------------------------
// K3: conv2 with folded weights w2' and per-tap bias bk.
// Direct coalesced LDG from g_gout [g][c][n]; per-co float4 STG.128 output.
// ---------------------------------------------------------------------------
__global__ void __launch_bounds__(256, 3) k_conv2(
    const float* __restrict__ b2,
    float* __restrict__ out)
{
    __shared__ __align__(16) float w2s[96 * 32];   // folded, [(c1*3+kt)*32 + co]
    __shared__ __align__(16) float bks[3 * 32];    // [kt*32 + co]
    __shared__ __align__(16) float b2s[32];

    int tid = threadIdx.x;
    for (int i = tid; i < 96 * 32; i += 256) w2s[i] = g_w2p[i];
    if (tid < 96) bks[tid] = g_bk[tid];
    if (tid < 32) b2s[tid] = b2[tid];
    __syncthreads();

    int cog = tid & 3;
    int ptg = tid >> 2;
    int co0 = cog * 8;
    int n0  = blockIdx.x * PTSB;
    int nb  = n0 + ptg * 4;
    bool alive = (nb < N_);
    int t = blockIdx.y;
    int b = blockIdx.z;

    bool v0 = (t - 1 >= 0);
    bool v2 = (t + 1 < T_);
    bool ld[3] = { v0 && alive, alive, v2 && alive };

    ull acc[4][4];
    #pragma unroll
    for (int cp = 0; cp < 4; cp++) {
        int coA = co0 + 2 * cp;
        int coB = coA + 1;
        float biasA = b2s[coA] + bks[32 + coA]
                    + (v0 ? bks[coA] : 0.0f) + (v2 ? bks[64 + coA] : 0.0f);
        float biasB = b2s[coB] + bks[32 + coB]
                    + (v0 ? bks[coB] : 0.0f) + (v2 ? bks[64 + coB] : 0.0f);
        ull bq = pack2(biasA, biasB);
        #pragma unroll
        for (int pt = 0; pt < 4; pt++) acc[pt][cp] = bq;
    }

    // plane (t-1) for c1 = 0
    const float* gbase = g_gout + ((size_t)(b * T_) + (t - 1)) * C_ * N_ + nb;
    #pragma unroll 2
    for (int ci = 0; ci < 32; ci++) {
        const float* gr = gbase + (size_t)ci * N_;
        float4 gv[3];
        #pragma unroll
        for (int kt = 0; kt < 3; kt++) {
            gv[kt] = ld[kt] ? *(const float4*)(gr + (size_t)kt * C_ * N_)
                            : make_float4(0.f, 0.f, 0.f, 0.f);
        }
        #pragma unroll
        for (int kt = 0; kt < 3; kt++) {
            ull in[4];
            in[0] = dup2(gv[kt].x); in[1] = dup2(gv[kt].y);
            in[2] = dup2(gv[kt].z); in[3] = dup2(gv[kt].w);
            const ulonglong2* wp = (const ulonglong2*)&w2s[(ci * 3 + kt) * 32 + co0];
            ulonglong2 wa = wp[0];
            ulonglong2 wb = wp[1];
            #pragma unroll
            for (int pt = 0; pt < 4; pt++) {
                ffma2(acc[pt][0], in[pt], wa.x);
                ffma2(acc[pt][1], in[pt], wa.y);
                ffma2(acc[pt][2], in[pt], wb.x);
                ffma2(acc[pt][3], in[pt], wb.y);
            }
        }
    }

    if (alive) {
        #pragma unroll
        for (int cp = 0; cp < 4; cp++) {
            float2 v0f = unpack2(acc[0][cp]);
            float2 v1f = unpack2(acc[1][cp]);
            float2 v2f = unpack2(acc[2][cp]);
            float2 v3f = unpack2(acc[3][cp]);
            int coA = co0 + 2 * cp;
            int coB = coA + 1;
            float4 lo = make_float4(v0f.x, v1f.x, v2f.x, v3f.x);
            float4 hi = make_float4(v0f.y, v1f.y, v2f.y, v3f.y);
            *(float4*)(out + ((size_t)(b * C_ + coA) * T_ + t) * N_ + nb) = lo;
            *(float4*)(out + ((size_t)(b * C_ + coB) * T_ + t) * N_ + nb) = hi;
        }
    }
}

// ---------------------------------------------------------------------------
// Launcher
// ---------------------------------------------------------------------------
extern "C" void kernel_launch(void* const* d_in, const int* in_sizes, int n_in,
                              void* d_out, int out_size) {
    const float* x     = (const float*)d_in[0];
    const void*  edges = d_in[1];
    const float* w1    = (const float*)d_in[2];
    const float* b1    = (const float*)d_in[3];
    const float* gcn_w = (const float*)d_in[4];
    const float* gcn_b = (const float*)d_in[5];
    const float* w2    = (const float*)d_in[6];
    const float* b2    = (const float*)d_in[7];
    float* out = (float*)d_out;

    dim3 g1(NBLK1 + 1, T_ / 2, B_);   // +1 block does CSR prep + weight folding
    k_conv1<<<g1, 256>>>(x, edges, w1, b1, gcn_w, gcn_b, w2);

    dim3 ga(N_ / 8, BT_ / 4);
    k_agg<<<ga, 256>>>();

    dim3 g2(NBLK2, T_, B_);
    k_conv2<<<g2, 256>>>(b2, out);
}